// round 3
// baseline (speedup 1.0000x reference)
#include <cuda_runtime.h>

#define B_  64
#define L_  200
#define NS_ 1000
#define D_  128
#define M_  50
#define BL_ (B_*L_)
#define WSTR 64   // padded w-row stride (slots 50..63 zero)

// -------- scratch (device globals; no allocation allowed) --------
__device__ float g_wtab[1024*WSTR];   // softmax weights per skill (padded)
__device__ float g_etab[2016*D_];     // sigmoid erase per x
__device__ float g_atab[2016*D_];     // tanh add per x
__device__ float g_kftab[1024*D_];    // k_emb[s] @ f_Wk^T (no bias/act)
__device__ float g_read[BL_*D_];      // read vectors

__device__ __forceinline__ float fsigmoid(float x){ return 1.f/(1.f+__expf(-x)); }
__device__ __forceinline__ float ftanh(float x){ float y; asm("tanh.approx.f32 %0, %1;":"=f"(y):"f"(x)); return y; }
__device__ __forceinline__ float dot4(float4 a, float4 b){
    return fmaf(a.x, b.x, fmaf(a.y, b.y, fmaf(a.z, b.z, a.w*b.w)));
}

// =====================================================================
// Kernel A: build all tables. 158 blocks x 256 threads.
//   blocks 0..62   : e-table  (32 v_emb rows each, covers 2016)
//   blocks 63..125 : a-table
//   blocks 126..157: w (softmax) + kf tables (32 k_emb rows each, 1024)
// Weights read directly from GMEM (L1-cached, dot-product form); smem
// holds only the 16KB gathered activation tile.
// =====================================================================
extern "C" __global__ void __launch_bounds__(256)
kA_tables(const float* __restrict__ k_emb, const float* __restrict__ v_emb,
          const float* __restrict__ Mk,
          const float* __restrict__ e_W, const float* __restrict__ e_b,
          const float* __restrict__ a_W, const float* __restrict__ a_b,
          const float* __restrict__ f_W)
{
    __shared__ float sx[32*D_];          // 16KB activation tile
    const int tid = threadIdx.x;
    const int tx = tid & 31, ty = tid >> 5;
    const int r0 = ty * 4, c0 = tx * 4;
    const int bid = blockIdx.x;

    if (bid < 126) {
        // ---------------- e-table or a-table ----------------
        const bool is_e = (bid < 63);
        const int rowblk = is_e ? bid : (bid - 63);
        const int rbase = rowblk * 32;
        const float* W  = is_e ? e_W : a_W;
        const float* bv = is_e ? e_b : a_b;

        {
            float4* s4 = (float4*)sx;
            const float4* ve4 = (const float4*)v_emb;
            for (int u = tid; u < 32*32; u += 256) {
                int r = u >> 5, c = u & 31;
                int rr = min(rbase + r, 2*NS_ - 1);
                s4[r*32 + c] = ve4[rr*32 + c];
            }
        }
        __syncthreads();

        float acc[4][4] = {};
        const float4* s4 = (const float4*)sx;
        const float4* W4 = (const float4*)W;
        #pragma unroll 4
        for (int k4 = 0; k4 < 32; k4++) {
            float4 vr[4], w[4];
            #pragma unroll
            for (int i = 0; i < 4; i++) vr[i] = s4[(r0+i)*32 + k4];
            #pragma unroll
            for (int c = 0; c < 4; c++) w[c] = __ldg(&W4[(c0+c)*32 + k4]);
            #pragma unroll
            for (int i = 0; i < 4; i++)
                #pragma unroll
                for (int c = 0; c < 4; c++)
                    acc[i][c] = fmaf(vr[i].x, w[c].x,
                                fmaf(vr[i].y, w[c].y,
                                fmaf(vr[i].z, w[c].z,
                                fmaf(vr[i].w, w[c].w, acc[i][c]))));
        }
        float4 bb = *(const float4*)&bv[c0];
        #pragma unroll
        for (int i = 0; i < 4; i++) {
            int row = rbase + r0 + i;
            float4 o;
            if (is_e) {
                o.x = fsigmoid(acc[i][0] + bb.x); o.y = fsigmoid(acc[i][1] + bb.y);
                o.z = fsigmoid(acc[i][2] + bb.z); o.w = fsigmoid(acc[i][3] + bb.w);
                *(float4*)&g_etab[(size_t)row*D_ + c0] = o;
            } else {
                o.x = ftanh(acc[i][0] + bb.x); o.y = ftanh(acc[i][1] + bb.y);
                o.z = ftanh(acc[i][2] + bb.z); o.w = ftanh(acc[i][3] + bb.w);
                *(float4*)&g_atab[(size_t)row*D_ + c0] = o;
            }
        }
    } else {
        // ---------------- w + kf tables ----------------
        const int rbase = (bid - 126) * 32;
        {
            float4* s4 = (float4*)sx;
            const float4* ke4 = (const float4*)k_emb;
            for (int u = tid; u < 32*32; u += 256) {
                int r = u >> 5, c = u & 31;
                int rr = min(rbase + r, NS_ - 1);
                s4[r*32 + c] = ke4[rr*32 + c];
            }
        }
        __syncthreads();
        const float4* s4 = (const float4*)sx;

        // logits + softmax -> g_wtab
        {
            const int m0 = tx, m1 = tx + 32;
            const int m1c = min(m1, M_ - 1);
            const float4* Mk4 = (const float4*)Mk;
            float a0[4] = {}, a1[4] = {};
            #pragma unroll 4
            for (int k4 = 0; k4 < 32; k4++) {
                float4 mk0 = __ldg(&Mk4[m0*32 + k4]);
                float4 mk1 = __ldg(&Mk4[m1c*32 + k4]);
                #pragma unroll
                for (int i = 0; i < 4; i++) {
                    float4 kr = s4[(r0+i)*32 + k4];
                    a0[i] = fmaf(kr.x, mk0.x, fmaf(kr.y, mk0.y, fmaf(kr.z, mk0.z, fmaf(kr.w, mk0.w, a0[i]))));
                    a1[i] = fmaf(kr.x, mk1.x, fmaf(kr.y, mk1.y, fmaf(kr.z, mk1.z, fmaf(kr.w, mk1.w, a1[i]))));
                }
            }
            #pragma unroll
            for (int i = 0; i < 4; i++) {
                float v0 = a0[i];
                float v1 = (m1 < M_) ? a1[i] : -1e30f;
                float mx = fmaxf(v0, v1);
                #pragma unroll
                for (int o = 16; o >= 1; o >>= 1) mx = fmaxf(mx, __shfl_xor_sync(0xffffffffu, mx, o));
                float e0 = __expf(v0 - mx);
                float e1 = (m1 < M_) ? __expf(v1 - mx) : 0.f;
                float s = e0 + e1;
                #pragma unroll
                for (int o = 16; o >= 1; o >>= 1) s += __shfl_xor_sync(0xffffffffu, s, o);
                float inv = __frcp_rn(s);
                int row = rbase + r0 + i;
                g_wtab[row*WSTR + m0] = e0 * inv;
                g_wtab[row*WSTR + m1] = e1 * inv;   // zero in pad region
            }
        }

        // kf GEMM -> g_kftab : fw row c = f_W[c][128+k]
        {
            float acc[4][4] = {};
            const float4* fW4 = (const float4*)f_W;   // row stride 64 f4
            #pragma unroll 4
            for (int k4 = 0; k4 < 32; k4++) {
                float4 kr[4], w[4];
                #pragma unroll
                for (int i = 0; i < 4; i++) kr[i] = s4[(r0+i)*32 + k4];
                #pragma unroll
                for (int c = 0; c < 4; c++) w[c] = __ldg(&fW4[(c0+c)*64 + 32 + k4]);
                #pragma unroll
                for (int i = 0; i < 4; i++)
                    #pragma unroll
                    for (int c = 0; c < 4; c++)
                        acc[i][c] = fmaf(kr[i].x, w[c].x,
                                    fmaf(kr[i].y, w[c].y,
                                    fmaf(kr[i].z, w[c].z,
                                    fmaf(kr[i].w, w[c].w, acc[i][c]))));
            }
            #pragma unroll
            for (int i = 0; i < 4; i++) {
                int row = rbase + r0 + i;
                float4 o; o.x = acc[i][0]; o.y = acc[i][1]; o.z = acc[i][2]; o.w = acc[i][3];
                *(float4*)&g_kftab[(size_t)row*D_ + c0] = o;
            }
        }
    }
}

// =====================================================================
// Kernel B: sequential scan; grid (B, 2 d-halves) x 512 threads (16 warps).
// thread = (mg in 0..7, dl in 0..63); 8 m-slots per thread in registers.
// =====================================================================
extern "C" __global__ void __launch_bounds__(512)
kB_scan(const int* __restrict__ skills, const int* __restrict__ responses,
        const float* __restrict__ Mv0)
{
    __shared__ int s_sk[L_], s_x[L_];
    const int b   = blockIdx.x;
    const int tid = threadIdx.x;

    for (int t = tid; t < L_; t += 512) {
        int sk = skills[b*L_ + t];
        int r  = responses[b*L_ + t];
        int mr = (r > -1) ? r : 0;
        s_sk[t] = sk;
        s_x[t]  = sk + NS_ * mr;
    }
    __syncthreads();

    const int mg  = tid & 7;
    const int dl  = tid >> 3;
    const int d   = blockIdx.y * 64 + dl;
    const int mbase = mg * 8;

    float mv[8];
    #pragma unroll
    for (int i = 0; i < 8; i++) {
        int m = mbase + i;
        mv[i] = (m < M_) ? Mv0[m*D_ + d] : 0.f;
    }

    float* rp = g_read + (size_t)b*L_*D_ + d;

    float ev, av; float4 w4[2];
    {
        int xx = s_x[0], kk = s_sk[0];
        ev = __ldg(&g_etab[(size_t)xx*D_ + d]);
        av = __ldg(&g_atab[(size_t)xx*D_ + d]);
        const float4* wq = (const float4*)(g_wtab + kk*WSTR + mbase);
        w4[0] = __ldg(wq); w4[1] = __ldg(wq + 1);
    }

    for (int t = 0; t < L_; t++) {
        float ev_n = 0.f, av_n = 0.f;
        float4 wn[2] = {};
        if (t + 1 < L_) {
            int xx = s_x[t+1], kk = s_sk[t+1];
            ev_n = __ldg(&g_etab[(size_t)xx*D_ + d]);
            av_n = __ldg(&g_atab[(size_t)xx*D_ + d]);
            const float4* wq = (const float4*)(g_wtab + kk*WSTR + mbase);
            wn[0] = __ldg(wq); wn[1] = __ldg(wq + 1);
        }

        float rda[2] = {0.f, 0.f};
        #pragma unroll
        for (int j = 0; j < 2; j++) {
            float wv[4] = {w4[j].x, w4[j].y, w4[j].z, w4[j].w};
            #pragma unroll
            for (int s = 0; s < 4; s++) {
                int i = j*4 + s;
                float w = wv[s];
                rda[j] = fmaf(w, mv[i], rda[j]);   // read uses PRE-update Mv
                float g = fmaf(-ev, mv[i], av);    // a - e*mv
                mv[i] = fmaf(w, g, mv[i]);         // mv += w*(a - e*mv)
            }
        }
        float rd = rda[0] + rda[1];
        rd += __shfl_xor_sync(0xffffffffu, rd, 1);
        rd += __shfl_xor_sync(0xffffffffu, rd, 2);
        rd += __shfl_xor_sync(0xffffffffu, rd, 4);
        if (mg == 0) rp[t*D_] = rd;

        ev = ev_n; av = av_n;
        w4[0] = wn[0]; w4[1] = wn[1];
    }
}

// =====================================================================
// Kernel C: f = tanh(read @ f_Wr^T + kf_tab[skill] + f_b); p = sigmoid(f.p_W+p_b)
// 400 blocks x 256 threads, 32 rows/block; weights via L1, smem = 16KB tile.
// =====================================================================
extern "C" __global__ void __launch_bounds__(256)
kC_out(const int* __restrict__ skills,
       const float* __restrict__ f_W, const float* __restrict__ f_b,
       const float* __restrict__ p_W, const float* __restrict__ p_b,
       float* __restrict__ out)
{
    __shared__ float hx[32*D_];     // 16KB read tile
    __shared__ int s_sk[32];

    const int tid  = threadIdx.x;
    const int row0 = blockIdx.x * 32;

    if (tid < 32) s_sk[tid] = skills[row0 + tid];
    {
        float4* h4 = (float4*)hx;
        const float4* rd4 = (const float4*)g_read;
        for (int u = tid; u < 32*32; u += 256) {
            int r = u >> 5, c = u & 31;
            h4[r*32 + c] = rd4[(size_t)(row0 + r)*32 + c];
        }
    }
    __syncthreads();

    const int tx = tid & 31, ty = tid >> 5;
    const int r0 = ty * 4, c0 = tx * 4;

    float acc[4][4] = {};
    const float4* h4 = (const float4*)hx;
    const float4* fW4 = (const float4*)f_W;   // row stride 64 f4; read-half = first 32
    #pragma unroll 4
    for (int k4 = 0; k4 < 32; k4++) {
        float4 hr[4], w[4];
        #pragma unroll
        for (int i = 0; i < 4; i++) hr[i] = h4[(r0+i)*32 + k4];
        #pragma unroll
        for (int c = 0; c < 4; c++) w[c] = __ldg(&fW4[(c0+c)*64 + k4]);
        #pragma unroll
        for (int i = 0; i < 4; i++)
            #pragma unroll
            for (int c = 0; c < 4; c++)
                acc[i][c] = fmaf(hr[i].x, w[c].x,
                            fmaf(hr[i].y, w[c].y,
                            fmaf(hr[i].z, w[c].z,
                            fmaf(hr[i].w, w[c].w, acc[i][c]))));
    }
    float4 fb = *(const float4*)&f_b[c0];
    float4 pw = *(const float4*)&p_W[c0];
    float pb = p_b[0];
    #pragma unroll
    for (int i = 0; i < 4; i++) {
        int row = row0 + r0 + i;
        int sk = s_sk[r0 + i];
        float4 kf = *(const float4*)&g_kftab[(size_t)sk*D_ + c0];
        float f0 = ftanh(acc[i][0] + kf.x + fb.x);
        float f1 = ftanh(acc[i][1] + kf.y + fb.y);
        float f2 = ftanh(acc[i][2] + kf.z + fb.z);
        float f3 = ftanh(acc[i][3] + kf.w + fb.w);
        float pp = f0*pw.x + f1*pw.y + f2*pw.z + f3*pw.w;
        #pragma unroll
        for (int o = 16; o >= 1; o >>= 1) pp += __shfl_xor_sync(0xffffffffu, pp, o);
        if (tx == 0) {
            int bb = row / L_, t = row % L_;
            if (t >= 1) out[bb*(L_-1) + (t-1)] = fsigmoid(pp + pb);
        }
    }
}

// =====================================================================
extern "C" void kernel_launch(void* const* d_in, const int* in_sizes, int n_in,
                              void* d_out, int out_size)
{
    const int*   skills    = (const int*)  d_in[0];
    const int*   responses = (const int*)  d_in[1];
    const float* k_emb     = (const float*)d_in[2];
    const float* v_emb     = (const float*)d_in[3];
    const float* Mk        = (const float*)d_in[4];
    const float* Mv0       = (const float*)d_in[5];
    const float* e_W       = (const float*)d_in[6];
    const float* e_b       = (const float*)d_in[7];
    const float* a_W       = (const float*)d_in[8];
    const float* a_b       = (const float*)d_in[9];
    const float* f_W       = (const float*)d_in[10];
    const float* f_b       = (const float*)d_in[11];
    const float* p_W       = (const float*)d_in[12];
    const float* p_b       = (const float*)d_in[13];
    float* out = (float*)d_out;

    kA_tables<<<158, 256>>>(k_emb, v_emb, Mk, e_W, e_b, a_W, a_b, f_W);
    kB_scan<<<dim3(B_, 2), 512>>>(skills, responses, Mv0);
    kC_out<<<BL_/32, 256>>>(skills, f_W, f_b, p_W, p_b, out);
}

// round 4
// speedup vs baseline: 1.5334x; 1.5334x over previous
#include <cuda_runtime.h>

#define B_  64
#define L_  200
#define NS_ 1000
#define D_  128
#define M_  50
#define BL_ (B_*L_)
#define WSTR 64   // padded w-row stride (slots 50..63 zero)

// -------- scratch (device globals; no allocation allowed) --------
__device__ float g_wtab[1024*WSTR];   // softmax weights per skill (padded)
__device__ float g_etab[2016*D_];     // sigmoid erase per x
__device__ float g_atab[2016*D_];     // tanh add per x
__device__ float g_kftab[1024*D_];    // k_emb[s] @ f_Wk^T (no bias/act)
__device__ float g_read[BL_*D_];      // read vectors

__device__ __forceinline__ float fsigmoid(float x){ return 1.f/(1.f+__expf(-x)); }
__device__ __forceinline__ float ftanh(float x){ float y; asm("tanh.approx.f32 %0, %1;":"=f"(y):"f"(x)); return y; }

// =====================================================================
// Kernel A: build all tables. 190 blocks x 256 threads, 83KB smem
//  -> 2 blocks/SM. Block types:
//   [0,63)    e-table   : 32 v_emb rows, eWT in smem (transposed, pad 132)
//   [63,126)  a-table
//   [126,158) w-table   : softmax(k.Mk^T) via MkT in smem
//   [158,190) kf-table  : k_emb @ f_Wk^T via fkT in smem
// =====================================================================
extern "C" __global__ void __launch_bounds__(256, 2)
kA_tables(const float* __restrict__ k_emb, const float* __restrict__ v_emb,
          const float* __restrict__ Mk,
          const float* __restrict__ e_W, const float* __restrict__ e_b,
          const float* __restrict__ a_W, const float* __restrict__ a_b,
          const float* __restrict__ f_W)
{
    extern __shared__ float sm[];
    float* sx = sm;                 // 32*128 activation tile (16KB)
    float* sw = sm + 32*D_;         // weight region (transposed, pad 132) 67KB
    const int tid = threadIdx.x;
    const int tx = tid & 31, ty = tid >> 5;
    const int r0 = ty * 4, c0 = tx * 4;
    const int bid = blockIdx.x;

    if (bid < 126) {
        // ---------------- e-table or a-table ----------------
        const bool is_e = (bid < 63);
        const int rbase = (is_e ? bid : bid - 63) * 32;
        const float* W  = is_e ? e_W : a_W;
        const float* bv = is_e ? e_b : a_b;

        for (int i = tid; i < D_*D_; i += 256) {
            int d = i >> 7, k = i & 127;
            sw[k*132 + d] = W[i];            // transpose-stage (coalesced gmem)
        }
        {
            float4* s4 = (float4*)sx;
            const float4* ve4 = (const float4*)v_emb;
            for (int u = tid; u < 32*32; u += 256) {
                int r = u >> 5, c = u & 31;
                int rr = min(rbase + r, 2*NS_ - 1);
                s4[r*32 + c] = ve4[rr*32 + c];
            }
        }
        __syncthreads();

        float acc[4][4] = {};
        const float4* s4 = (const float4*)sx;
        #pragma unroll 4
        for (int k4 = 0; k4 < 32; k4++) {
            float4 vr[4];
            #pragma unroll
            for (int i = 0; i < 4; i++) vr[i] = s4[(r0+i)*32 + k4];
            #pragma unroll
            for (int s = 0; s < 4; s++) {
                int k = 4*k4 + s;
                float4 w = *(const float4*)&sw[k*132 + c0];
                #pragma unroll
                for (int i = 0; i < 4; i++) {
                    float vv = ((const float*)&vr[i])[s];
                    acc[i][0] = fmaf(vv, w.x, acc[i][0]);
                    acc[i][1] = fmaf(vv, w.y, acc[i][1]);
                    acc[i][2] = fmaf(vv, w.z, acc[i][2]);
                    acc[i][3] = fmaf(vv, w.w, acc[i][3]);
                }
            }
        }
        float4 bb = *(const float4*)&bv[c0];
        #pragma unroll
        for (int i = 0; i < 4; i++) {
            int row = rbase + r0 + i;
            float4 o;
            if (is_e) {
                o.x = fsigmoid(acc[i][0] + bb.x); o.y = fsigmoid(acc[i][1] + bb.y);
                o.z = fsigmoid(acc[i][2] + bb.z); o.w = fsigmoid(acc[i][3] + bb.w);
                *(float4*)&g_etab[(size_t)row*D_ + c0] = o;
            } else {
                o.x = ftanh(acc[i][0] + bb.x); o.y = ftanh(acc[i][1] + bb.y);
                o.z = ftanh(acc[i][2] + bb.z); o.w = ftanh(acc[i][3] + bb.w);
                *(float4*)&g_atab[(size_t)row*D_ + c0] = o;
            }
        }
    } else if (bid < 158) {
        // ---------------- w (softmax) table ----------------
        const int rbase = (bid - 126) * 32;
        float* MkT = sw;                      // 128*65
        for (int i = tid; i < M_*D_; i += 256) {
            int m = i >> 7, k = i & 127;
            MkT[k*65 + m] = Mk[i];
        }
        for (int i = tid; i < D_*14; i += 256) {
            int k = i / 14, m = 50 + (i % 14);
            MkT[k*65 + m] = 0.f;
        }
        {
            float4* s4 = (float4*)sx;
            const float4* ke4 = (const float4*)k_emb;
            for (int u = tid; u < 32*32; u += 256) {
                int r = u >> 5, c = u & 31;
                int rr = min(rbase + r, NS_ - 1);
                s4[r*32 + c] = ke4[rr*32 + c];
            }
        }
        __syncthreads();

        const int m0 = tx, m1 = tx + 32;
        float a0[4] = {}, a1[4] = {};
        const float4* s4 = (const float4*)sx;
        #pragma unroll 4
        for (int k4 = 0; k4 < 32; k4++) {
            float4 kr[4];
            #pragma unroll
            for (int i = 0; i < 4; i++) kr[i] = s4[(r0+i)*32 + k4];
            #pragma unroll
            for (int s = 0; s < 4; s++) {
                int k = 4*k4 + s;
                float mv0 = MkT[k*65 + m0];
                float mv1 = MkT[k*65 + m1];
                #pragma unroll
                for (int i = 0; i < 4; i++) {
                    float kv = ((const float*)&kr[i])[s];
                    a0[i] = fmaf(kv, mv0, a0[i]);
                    a1[i] = fmaf(kv, mv1, a1[i]);
                }
            }
        }
        #pragma unroll
        for (int i = 0; i < 4; i++) {
            float v0 = a0[i];
            float v1 = (m1 < M_) ? a1[i] : -1e30f;
            float mx = fmaxf(v0, v1);
            #pragma unroll
            for (int o = 16; o >= 1; o >>= 1) mx = fmaxf(mx, __shfl_xor_sync(0xffffffffu, mx, o));
            float e0 = __expf(v0 - mx);
            float e1 = (m1 < M_) ? __expf(v1 - mx) : 0.f;
            float s = e0 + e1;
            #pragma unroll
            for (int o = 16; o >= 1; o >>= 1) s += __shfl_xor_sync(0xffffffffu, s, o);
            float inv = __frcp_rn(s);
            int row = rbase + r0 + i;
            g_wtab[row*WSTR + m0] = e0 * inv;
            g_wtab[row*WSTR + m1] = e1 * inv;   // zero in pad region
        }
    } else {
        // ---------------- kf table ----------------
        const int rbase = (bid - 158) * 32;
        for (int i = tid; i < D_*D_; i += 256) {
            int d = i >> 7, k = i & 127;
            sw[k*132 + d] = f_W[d*(2*D_) + D_ + k];   // k-half of f_W, transposed
        }
        {
            float4* s4 = (float4*)sx;
            const float4* ke4 = (const float4*)k_emb;
            for (int u = tid; u < 32*32; u += 256) {
                int r = u >> 5, c = u & 31;
                int rr = min(rbase + r, NS_ - 1);
                s4[r*32 + c] = ke4[rr*32 + c];
            }
        }
        __syncthreads();

        float acc[4][4] = {};
        const float4* s4 = (const float4*)sx;
        #pragma unroll 4
        for (int k4 = 0; k4 < 32; k4++) {
            float4 kr[4];
            #pragma unroll
            for (int i = 0; i < 4; i++) kr[i] = s4[(r0+i)*32 + k4];
            #pragma unroll
            for (int s = 0; s < 4; s++) {
                int k = 4*k4 + s;
                float4 w = *(const float4*)&sw[k*132 + c0];
                #pragma unroll
                for (int i = 0; i < 4; i++) {
                    float kv = ((const float*)&kr[i])[s];
                    acc[i][0] = fmaf(kv, w.x, acc[i][0]);
                    acc[i][1] = fmaf(kv, w.y, acc[i][1]);
                    acc[i][2] = fmaf(kv, w.z, acc[i][2]);
                    acc[i][3] = fmaf(kv, w.w, acc[i][3]);
                }
            }
        }
        #pragma unroll
        for (int i = 0; i < 4; i++) {
            int row = rbase + r0 + i;
            float4 o; o.x = acc[i][0]; o.y = acc[i][1]; o.z = acc[i][2]; o.w = acc[i][3];
            *(float4*)&g_kftab[(size_t)row*D_ + c0] = o;
        }
    }
}

// =====================================================================
// Kernel B: sequential scan; grid (B, 2 d-halves) x 512 threads.
// Depth-2 prefetch of table gathers to hide L2 latency.
// =====================================================================
extern "C" __global__ void __launch_bounds__(512)
kB_scan(const int* __restrict__ skills, const int* __restrict__ responses,
        const float* __restrict__ Mv0)
{
    __shared__ int s_sk[L_], s_x[L_];
    const int b   = blockIdx.x;
    const int tid = threadIdx.x;

    for (int t = tid; t < L_; t += 512) {
        int sk = skills[b*L_ + t];
        int r  = responses[b*L_ + t];
        int mr = (r > -1) ? r : 0;
        s_sk[t] = sk;
        s_x[t]  = sk + NS_ * mr;
    }
    __syncthreads();

    const int mg  = tid & 7;
    const int dl  = tid >> 3;
    const int d   = blockIdx.y * 64 + dl;
    const int mbase = mg * 8;

    float mv[8];
    #pragma unroll
    for (int i = 0; i < 8; i++) {
        int m = mbase + i;
        mv[i] = (m < M_) ? Mv0[m*D_ + d] : 0.f;
    }

    float* rp = g_read + (size_t)b*L_*D_ + d;

    float ev0, av0, ev1, av1;
    float4 w0[2], w1[2];
    {
        int xx = s_x[0], kk = s_sk[0];
        ev0 = __ldg(&g_etab[(size_t)xx*D_ + d]);
        av0 = __ldg(&g_atab[(size_t)xx*D_ + d]);
        const float4* wq = (const float4*)(g_wtab + kk*WSTR + mbase);
        w0[0] = __ldg(wq); w0[1] = __ldg(wq + 1);
        xx = s_x[1]; kk = s_sk[1];
        ev1 = __ldg(&g_etab[(size_t)xx*D_ + d]);
        av1 = __ldg(&g_atab[(size_t)xx*D_ + d]);
        wq = (const float4*)(g_wtab + kk*WSTR + mbase);
        w1[0] = __ldg(wq); w1[1] = __ldg(wq + 1);
    }

    for (int t = 0; t < L_; t++) {
        float ev2 = 0.f, av2 = 0.f;
        float4 w2[2] = {};
        if (t + 2 < L_) {
            int xx = s_x[t+2], kk = s_sk[t+2];
            ev2 = __ldg(&g_etab[(size_t)xx*D_ + d]);
            av2 = __ldg(&g_atab[(size_t)xx*D_ + d]);
            const float4* wq = (const float4*)(g_wtab + kk*WSTR + mbase);
            w2[0] = __ldg(wq); w2[1] = __ldg(wq + 1);
        }

        float rda[2] = {0.f, 0.f};
        #pragma unroll
        for (int j = 0; j < 2; j++) {
            float wv[4] = {w0[j].x, w0[j].y, w0[j].z, w0[j].w};
            #pragma unroll
            for (int s = 0; s < 4; s++) {
                int i = j*4 + s;
                float w = wv[s];
                rda[j] = fmaf(w, mv[i], rda[j]);   // read uses PRE-update Mv
                float g = fmaf(-ev0, mv[i], av0);  // a - e*mv
                mv[i] = fmaf(w, g, mv[i]);         // mv += w*(a - e*mv)
            }
        }
        float rd = rda[0] + rda[1];
        rd += __shfl_xor_sync(0xffffffffu, rd, 1);
        rd += __shfl_xor_sync(0xffffffffu, rd, 2);
        rd += __shfl_xor_sync(0xffffffffu, rd, 4);
        if (mg == 0) rp[t*D_] = rd;

        ev0 = ev1; av0 = av1; w0[0] = w1[0]; w0[1] = w1[1];
        ev1 = ev2; av1 = av2; w1[0] = w2[0]; w1[1] = w2[1];
    }
}

// =====================================================================
// Kernel C: f = tanh(read @ f_Wr^T + kf_tab[skill] + f_b); p = sigmoid(f.p_W+p_b)
// 200 blocks x 256 threads, 64 rows/block; 99KB smem -> 2 blocks/SM.
// =====================================================================
extern "C" __global__ void __launch_bounds__(256, 2)
kC_out(const int* __restrict__ skills,
       const float* __restrict__ f_W, const float* __restrict__ f_b,
       const float* __restrict__ p_W, const float* __restrict__ p_b,
       float* __restrict__ out)
{
    extern __shared__ float sm[];
    float* hx  = sm;                 // 64*128 read tile (32KB)
    float* fWT = sm + 64*D_;         // 128*132 (read-half of f_W, transposed) 67KB
    __shared__ int s_sk[64];

    const int tid  = threadIdx.x;
    const int row0 = blockIdx.x * 64;

    if (tid < 64) s_sk[tid] = skills[row0 + tid];
    for (int i = tid; i < D_*D_; i += 256) {
        int d = i >> 7, k = i & 127;
        fWT[k*132 + d] = f_W[d*(2*D_) + k];   // read-half, transposed
    }
    {
        float4* h4 = (float4*)hx;
        const float4* rd4 = (const float4*)g_read;
        for (int u = tid; u < 64*32; u += 256) {
            int r = u >> 5, c = u & 31;
            h4[r*32 + c] = rd4[(size_t)(row0 + r)*32 + c];
        }
    }
    __syncthreads();

    const int tx = tid & 31, ty = tid >> 5;
    const int r0 = ty * 8, c0 = tx * 4;

    float acc[8][4] = {};
    const float4* h4 = (const float4*)hx;
    #pragma unroll 2
    for (int k4 = 0; k4 < 32; k4++) {
        #pragma unroll
        for (int s = 0; s < 4; s++) {
            int k = k4*4 + s;
            float4 w = *(const float4*)&fWT[k*132 + c0];
            #pragma unroll
            for (int i = 0; i < 8; i++) {
                float hv = hx[(r0+i)*D_ + k];
                acc[i][0] = fmaf(hv, w.x, acc[i][0]);
                acc[i][1] = fmaf(hv, w.y, acc[i][1]);
                acc[i][2] = fmaf(hv, w.z, acc[i][2]);
                acc[i][3] = fmaf(hv, w.w, acc[i][3]);
            }
        }
    }
    float4 fb = *(const float4*)&f_b[c0];
    float4 pw = *(const float4*)&p_W[c0];
    float pb = p_b[0];
    #pragma unroll
    for (int i = 0; i < 8; i++) {
        int row = row0 + r0 + i;
        int sk = s_sk[r0 + i];
        float4 kf = *(const float4*)&g_kftab[(size_t)sk*D_ + c0];
        float f0 = ftanh(acc[i][0] + kf.x + fb.x);
        float f1 = ftanh(acc[i][1] + kf.y + fb.y);
        float f2 = ftanh(acc[i][2] + kf.z + fb.z);
        float f3 = ftanh(acc[i][3] + kf.w + fb.w);
        float pp = f0*pw.x + f1*pw.y + f2*pw.z + f3*pw.w;
        #pragma unroll
        for (int o = 16; o >= 1; o >>= 1) pp += __shfl_xor_sync(0xffffffffu, pp, o);
        if (tx == 0) {
            int bb = row / L_, t = row % L_;
            if (t >= 1) out[bb*(L_-1) + (t-1)] = fsigmoid(pp + pb);
        }
    }
}

// =====================================================================
extern "C" void kernel_launch(void* const* d_in, const int* in_sizes, int n_in,
                              void* d_out, int out_size)
{
    const int*   skills    = (const int*)  d_in[0];
    const int*   responses = (const int*)  d_in[1];
    const float* k_emb     = (const float*)d_in[2];
    const float* v_emb     = (const float*)d_in[3];
    const float* Mk        = (const float*)d_in[4];
    const float* Mv0       = (const float*)d_in[5];
    const float* e_W       = (const float*)d_in[6];
    const float* e_b       = (const float*)d_in[7];
    const float* a_W       = (const float*)d_in[8];
    const float* a_b       = (const float*)d_in[9];
    const float* f_W       = (const float*)d_in[10];
    const float* f_b       = (const float*)d_in[11];
    const float* p_W       = (const float*)d_in[12];
    const float* p_b       = (const float*)d_in[13];
    float* out = (float*)d_out;

    const size_t SZA = (size_t)(32*D_ + D_*132) * sizeof(float);   //  83968
    const size_t SZC = (size_t)(64*D_ + D_*132) * sizeof(float);   // 100352

    cudaFuncSetAttribute(kA_tables, cudaFuncAttributeMaxDynamicSharedMemorySize, (int)SZA);
    cudaFuncSetAttribute(kC_out,    cudaFuncAttributeMaxDynamicSharedMemorySize, (int)SZC);

    kA_tables<<<190, 256, SZA>>>(k_emb, v_emb, Mk, e_W, e_b, a_W, a_b, f_W);
    kB_scan<<<dim3(B_, 2), 512>>>(skills, responses, Mv0);
    kC_out<<<BL_/64, 256, SZC>>>(skills, f_W, f_b, p_W, p_b, out);
}